// round 7
// baseline (speedup 1.0000x reference)
#include <cuda_runtime.h>
#include <math.h>
#include <stdint.h>

#define IN_CH   512
#define NHEADS  8
#define H1DIM   64
#define OUT_CH  128
#define NMAX    50000
#define EMAX    800000
#define ETOT    (EMAX + NMAX)

// ------------------ scratch (static device globals; no allocs) ---------------
__device__ float g_h1   [NMAX * H1DIM];
__device__ float g_s1   [NMAX * NHEADS];
__device__ float g_d1   [NMAX * NHEADS];
__device__ float g_h1b  [NMAX * H1DIM];
__device__ float g_h2   [NMAX * OUT_CH];
__device__ float g_s2   [NMAX];
__device__ float g_d2   [NMAX];
__device__ int   g_deg   [NMAX];
__device__ int   g_rowptr[NMAX + 1];
__device__ int   g_cur   [NMAX];
__device__ int   g_csrc  [ETOT];
__device__ int   g_blocksum[16];
__device__ int   g_blockoff[16];

// ------------------ tf32 helpers ---------------------------------------------
__device__ __forceinline__ unsigned f2tf(float x)
{
    unsigned u;
    asm("cvt.rna.tf32.f32 %0, %1;" : "=r"(u) : "f"(x));
    return u;
}

__device__ __forceinline__ float2 split2(float x)
{
    unsigned hb = f2tf(x);
    float hf = __uint_as_float(hb);
    return make_float2(hf, __uint_as_float(f2tf(x - hf)));
}

__device__ __forceinline__ void mma_tf32(float* c, const unsigned* a, const unsigned* b)
{
    asm volatile(
        "mma.sync.aligned.m16n8k8.row.col.f32.tf32.tf32.f32 "
        "{%0,%1,%2,%3}, {%4,%5,%6,%7}, {%8,%9}, {%0,%1,%2,%3};\n"
        : "+f"(c[0]), "+f"(c[1]), "+f"(c[2]), "+f"(c[3])
        : "r"(a[0]), "r"(a[1]), "r"(a[2]), "r"(a[3]), "r"(b[0]), "r"(b[1]));
}

// ------------------ 3xTF32 GEMM: double-buffered, hi/lo-interleaved ----------
#define GBM 128
#define GBN 64
#define GBK 16
#define ASTRIDE 132            // float2 units; % 16 == 4 -> conflict-free
#define BSTRIDE 68
#define ASZ (GBK * ASTRIDE)
#define BSZ (GBK * BSTRIDE)
#define GEMM_SMEM ((2 * (ASZ + BSZ)) * (int)sizeof(float2))

extern __shared__ float2 s_mem[];

// C[M,N] = A[M,K] @ B[K,N]; fuse!=0 also writes per-head attention dots.
__global__ void __launch_bounds__(256)
gemm_tf32(const float* __restrict__ A, const float* __restrict__ B,
          float* __restrict__ C, int M, int N, int K,
          const float* __restrict__ asv, const float* __restrict__ adv,
          float* __restrict__ sout, float* __restrict__ dout, int fuse)
{
    float2* ASb = s_mem;             // [2][GBK][ASTRIDE]
    float2* BSb = s_mem + 2 * ASZ;   // [2][GBK][BSTRIDE]

    int tid  = threadIdx.x;
    int w    = tid >> 5, lane = tid & 31;
    int g    = lane >> 2, tig = lane & 3;
    int wm   = (w & 3) * 32;
    int wn   = (w >> 2) * 32;
    int m0   = blockIdx.x * GBM;
    int n0   = blockIdx.y * GBN;

    // A loader mapping: 2 float4 / thread
    int aq0 = tid >> 7, ar0 = tid & 127;
    int aq1 = (tid + 256) >> 7, ar1 = (tid + 256) & 127;
    // B loader mapping: 4 floats / thread
    int nl = tid & 63, kb = (tid >> 6) * 4;

    float4 areg[2];
    float  breg[4];

    auto load_global = [&](int kt) {
        int k0 = kt * GBK;
        int gr0 = m0 + ar0, gr1 = m0 + ar1;
        areg[0] = (gr0 < M) ? *(const float4*)(A + (size_t)gr0 * K + k0 + aq0 * 4)
                            : make_float4(0.f, 0.f, 0.f, 0.f);
        areg[1] = (gr1 < M) ? *(const float4*)(A + (size_t)gr1 * K + k0 + aq1 * 4)
                            : make_float4(0.f, 0.f, 0.f, 0.f);
#pragma unroll
        for (int t = 0; t < 4; t++)
            breg[t] = B[(size_t)(k0 + kb + t) * N + n0 + nl];
    };

    auto store_tile = [&](int st) {
        float2* As = ASb + st * ASZ;
        float2* Bs = BSb + st * BSZ;
        {
            float e[4] = {areg[0].x, areg[0].y, areg[0].z, areg[0].w};
#pragma unroll
            for (int t = 0; t < 4; t++)
                As[(aq0 * 4 + t) * ASTRIDE + ar0] = split2(e[t]);
        }
        {
            float e[4] = {areg[1].x, areg[1].y, areg[1].z, areg[1].w};
#pragma unroll
            for (int t = 0; t < 4; t++)
                As[(aq1 * 4 + t) * ASTRIDE + ar1] = split2(e[t]);
        }
#pragma unroll
        for (int t = 0; t < 4; t++)
            Bs[(kb + t) * BSTRIDE + nl] = split2(breg[t]);
    };

    float acc[2][4][4];
#pragma unroll
    for (int i = 0; i < 2; i++)
#pragma unroll
        for (int j = 0; j < 4; j++)
#pragma unroll
            for (int r = 0; r < 4; r++) acc[i][j][r] = 0.f;

    auto compute_tile = [&](int st) {
        const float2* As = ASb + st * ASZ;
        const float2* Bs = BSb + st * BSZ;
#pragma unroll
        for (int ks = 0; ks < GBK; ks += 8) {
            float2 af[2][4], bf[4][2];
#pragma unroll
            for (int i = 0; i < 2; i++) {
                int rb = wm + i * 16;
                af[i][0] = As[(ks + tig    ) * ASTRIDE + rb + g    ];
                af[i][1] = As[(ks + tig    ) * ASTRIDE + rb + g + 8];
                af[i][2] = As[(ks + tig + 4) * ASTRIDE + rb + g    ];
                af[i][3] = As[(ks + tig + 4) * ASTRIDE + rb + g + 8];
            }
#pragma unroll
            for (int j = 0; j < 4; j++) {
                int nb = wn + j * 8;
                bf[j][0] = Bs[(ks + tig    ) * BSTRIDE + nb + g];
                bf[j][1] = Bs[(ks + tig + 4) * BSTRIDE + nb + g];
            }
            unsigned ah[2][4], al[2][4], bh[4][2], bl[4][2];
#pragma unroll
            for (int i = 0; i < 2; i++)
#pragma unroll
                for (int r = 0; r < 4; r++) {
                    ah[i][r] = __float_as_uint(af[i][r].x);
                    al[i][r] = __float_as_uint(af[i][r].y);
                }
#pragma unroll
            for (int j = 0; j < 4; j++)
#pragma unroll
                for (int r = 0; r < 2; r++) {
                    bh[j][r] = __float_as_uint(bf[j][r].x);
                    bl[j][r] = __float_as_uint(bf[j][r].y);
                }
#pragma unroll
            for (int i = 0; i < 2; i++)
#pragma unroll
                for (int j = 0; j < 4; j++) {
                    mma_tf32(acc[i][j], ah[i], bh[j]);
                    mma_tf32(acc[i][j], al[i], bh[j]);
                    mma_tf32(acc[i][j], ah[i], bl[j]);
                }
        }
    };

    const int T = K / GBK;
    load_global(0);
    store_tile(0);
    __syncthreads();
    for (int t = 0; t < T; t++) {
        int st = t & 1;
        if (t + 1 < T) load_global(t + 1);
        compute_tile(st);
        if (t + 1 < T) store_tile(st ^ 1);
        __syncthreads();
    }

    // epilogue: store C
#pragma unroll
    for (int i = 0; i < 2; i++) {
#pragma unroll
        for (int j = 0; j < 4; j++) {
            int row = m0 + wm + i * 16 + g;
            int col = n0 + wn + j * 8 + 2 * tig;
            if (row < M)
                *(float2*)(C + (size_t)row * N + col) =
                    make_float2(acc[i][j][0], acc[i][j][1]);
            if (row + 8 < M)
                *(float2*)(C + (size_t)(row + 8) * N + col) =
                    make_float2(acc[i][j][2], acc[i][j][3]);
        }
    }

    // fused per-head attention dots (layer 1: N==64, head = 8 cols)
    if (fuse) {
#pragma unroll
        for (int i = 0; i < 2; i++) {
            int r0 = m0 + wm + i * 16 + g;
#pragma unroll
            for (int j = 0; j < 4; j++) {
                int col = wn + j * 8 + 2 * tig;
                float s0 = acc[i][j][0] * asv[col] + acc[i][j][1] * asv[col + 1];
                float d0 = acc[i][j][0] * adv[col] + acc[i][j][1] * adv[col + 1];
                float s1 = acc[i][j][2] * asv[col] + acc[i][j][3] * asv[col + 1];
                float d1 = acc[i][j][2] * adv[col] + acc[i][j][3] * adv[col + 1];
#pragma unroll
                for (int off = 1; off < 4; off <<= 1) {
                    s0 += __shfl_xor_sync(0xffffffffu, s0, off);
                    d0 += __shfl_xor_sync(0xffffffffu, d0, off);
                    s1 += __shfl_xor_sync(0xffffffffu, s1, off);
                    d1 += __shfl_xor_sync(0xffffffffu, d1, off);
                }
                if (tig == 0) {
                    int h = (wn >> 3) + j;
                    if (r0 < M)     { sout[r0 * NHEADS + h] = s0;
                                      dout[r0 * NHEADS + h] = d0; }
                    if (r0 + 8 < M) { sout[(r0 + 8) * NHEADS + h] = s1;
                                      dout[(r0 + 8) * NHEADS + h] = d1; }
                }
            }
        }
    }
}

// ------------------ CSR build ------------------------------------------------
__global__ void count_kernel(const int* __restrict__ dst, int ne, int n)
{
    int i = blockIdx.x * blockDim.x + threadIdx.x;
    if (i >= ne + n) return;
    int d = (i < ne) ? dst[i] : (i - ne);
    atomicAdd(&g_deg[d], 1);
}

__global__ void __launch_bounds__(1024) scan1_kernel(int n)
{
    __shared__ int warpsums[32];
    int tid = threadIdx.x, lane = tid & 31, wid = tid >> 5;
    int i0 = blockIdx.x * 4096 + tid * 4;
    int v[4];
#pragma unroll
    for (int k = 0; k < 4; k++) {
        int i = i0 + k;
        v[k] = (i < n) ? g_deg[i] : 0;
    }
    int tsum = v[0] + v[1] + v[2] + v[3];
    int x = tsum;
#pragma unroll
    for (int off = 1; off < 32; off <<= 1) {
        int t = __shfl_up_sync(0xffffffffu, x, off);
        if (lane >= off) x += t;
    }
    if (lane == 31) warpsums[wid] = x;
    __syncthreads();
    if (wid == 0) {
        int wv = warpsums[lane];
#pragma unroll
        for (int off = 1; off < 32; off <<= 1) {
            int t = __shfl_up_sync(0xffffffffu, wv, off);
            if (lane >= off) wv += t;
        }
        warpsums[lane] = wv;
    }
    __syncthreads();
    int warp_off = (wid > 0) ? warpsums[wid - 1] : 0;
    int run = warp_off + (x - tsum);
#pragma unroll
    for (int k = 0; k < 4; k++) {
        int i = i0 + k;
        if (i < n) g_rowptr[i] = run;
        run += v[k];
    }
    if (tid == 1023) g_blocksum[blockIdx.x] = warp_off + x;
}

__global__ void scan2_kernel(int nb, int n)
{
    int lane = threadIdx.x;
    int v = (lane < nb) ? g_blocksum[lane] : 0;
    int x = v;
#pragma unroll
    for (int off = 1; off < 32; off <<= 1) {
        int t = __shfl_up_sync(0xffffffffu, x, off);
        if (lane >= off) x += t;
    }
    if (lane < nb) g_blockoff[lane] = x - v;
    if (lane == 31) g_rowptr[n] = x;
}

__global__ void scan3_kernel(int n)
{
    int i = blockIdx.x * blockDim.x + threadIdx.x;
    if (i >= n) return;
    int r = g_rowptr[i] + g_blockoff[i >> 12];
    g_rowptr[i] = r;
    g_cur[i]    = r;
}

__global__ void scatter_kernel(const int* __restrict__ src,
                               const int* __restrict__ dst, int ne, int n)
{
    int i = blockIdx.x * blockDim.x + threadIdx.x;
    if (i >= ne + n) return;
    int s, d;
    if (i < ne) { s = src[i]; d = dst[i]; }
    else        { s = d = i - ne; }
    int pos = atomicAdd(&g_cur[d], 1);
    g_csrc[pos] = s;
}

// ------------------ layer-1 gather (4-wide unrolled) -------------------------
__global__ void __launch_bounds__(256) gather1_kernel(const float* __restrict__ bias, int n)
{
    int gw   = (blockIdx.x * blockDim.x + threadIdx.x) >> 5;
    int lane = threadIdx.x & 31;
    if (gw >= n) return;
    int h = lane >> 2;
    float dv = g_d1[gw * NHEADS + h];
    int j0 = g_rowptr[gw], j1 = g_rowptr[gw + 1];
    float acc0 = 0.f, acc1 = 0.f, den = 0.f;
    int j = j0;
    for (; j + 3 < j1; j += 4) {
        int s0 = g_csrc[j], s1 = g_csrc[j + 1], s2 = g_csrc[j + 2], s3 = g_csrc[j + 3];
        float a0 = g_s1[s0 * NHEADS + h] + dv;
        float a1 = g_s1[s1 * NHEADS + h] + dv;
        float a2 = g_s1[s2 * NHEADS + h] + dv;
        float a3 = g_s1[s3 * NHEADS + h] + dv;
        float2 h0 = *(const float2*)(g_h1 + s0 * H1DIM + lane * 2);
        float2 h1 = *(const float2*)(g_h1 + s1 * H1DIM + lane * 2);
        float2 h2 = *(const float2*)(g_h1 + s2 * H1DIM + lane * 2);
        float2 h3 = *(const float2*)(g_h1 + s3 * H1DIM + lane * 2);
        a0 = (a0 > 0.f) ? a0 : 0.2f * a0;  float e0 = __expf(a0);
        a1 = (a1 > 0.f) ? a1 : 0.2f * a1;  float e1 = __expf(a1);
        a2 = (a2 > 0.f) ? a2 : 0.2f * a2;  float e2 = __expf(a2);
        a3 = (a3 > 0.f) ? a3 : 0.2f * a3;  float e3 = __expf(a3);
        den += (e0 + e1) + (e2 + e3);
        acc0 = fmaf(e0, h0.x, acc0); acc1 = fmaf(e0, h0.y, acc1);
        acc0 = fmaf(e1, h1.x, acc0); acc1 = fmaf(e1, h1.y, acc1);
        acc0 = fmaf(e2, h2.x, acc0); acc1 = fmaf(e2, h2.y, acc1);
        acc0 = fmaf(e3, h3.x, acc0); acc1 = fmaf(e3, h3.y, acc1);
    }
    for (; j < j1; j++) {
        int s = g_csrc[j];
        float a = g_s1[s * NHEADS + h] + dv;
        a = (a > 0.f) ? a : 0.2f * a;
        float ea = __expf(a);
        den += ea;
        float2 hv = *(const float2*)(g_h1 + s * H1DIM + lane * 2);
        acc0 = fmaf(ea, hv.x, acc0);
        acc1 = fmaf(ea, hv.y, acc1);
    }
    float inv = 1.f / den;
    int c = lane * 2;
    float v0 = acc0 * inv + bias[c];
    float v1 = acc1 * inv + bias[c + 1];
    v0 = (v0 > 0.f) ? v0 : expm1f(v0);
    v1 = (v1 > 0.f) ? v1 : expm1f(v1);
    *(float2*)(g_h1b + gw * H1DIM + c) = make_float2(v0, v1);
}

// ------------------ layer-2 per-node attention coefficients ------------------
__global__ void sd2_kernel(const float* __restrict__ att_src,
                           const float* __restrict__ att_dst, int n)
{
    int gt   = blockIdx.x * blockDim.x + threadIdx.x;
    int node = gt >> 5;
    int lane = gt & 31;
    if (node >= n) return;
    float4 hv = *(const float4*)(g_h2 + (size_t)node * OUT_CH + lane * 4);
    float4 as = *(const float4*)(att_src + lane * 4);
    float4 ad = *(const float4*)(att_dst + lane * 4);
    float s = hv.x * as.x + hv.y * as.y + hv.z * as.z + hv.w * as.w;
    float d = hv.x * ad.x + hv.y * ad.y + hv.z * ad.z + hv.w * ad.w;
#pragma unroll
    for (int off = 16; off > 0; off >>= 1) {
        s += __shfl_down_sync(0xffffffffu, s, off);
        d += __shfl_down_sync(0xffffffffu, d, off);
    }
    if (lane == 0) { g_s2[node] = s; g_d2[node] = d; }
}

// ------------------ layer-2 gather (4-wide unrolled) -> final output ---------
__global__ void __launch_bounds__(256) gather2_kernel(const float* __restrict__ bias,
                                                      float* __restrict__ out, int n)
{
    int gw   = (blockIdx.x * blockDim.x + threadIdx.x) >> 5;
    int lane = threadIdx.x & 31;
    if (gw >= n) return;
    float dv = g_d2[gw];
    int j0 = g_rowptr[gw], j1 = g_rowptr[gw + 1];
    float a0 = 0.f, a1 = 0.f, a2 = 0.f, a3 = 0.f, den = 0.f;
    int j = j0;
    for (; j + 3 < j1; j += 4) {
        int s0 = g_csrc[j], s1 = g_csrc[j + 1], s2 = g_csrc[j + 2], s3 = g_csrc[j + 3];
        float x0 = g_s2[s0] + dv, x1 = g_s2[s1] + dv;
        float x2 = g_s2[s2] + dv, x3 = g_s2[s3] + dv;
        float4 h0 = *(const float4*)(g_h2 + (size_t)s0 * OUT_CH + lane * 4);
        float4 h1 = *(const float4*)(g_h2 + (size_t)s1 * OUT_CH + lane * 4);
        float4 h2 = *(const float4*)(g_h2 + (size_t)s2 * OUT_CH + lane * 4);
        float4 h3 = *(const float4*)(g_h2 + (size_t)s3 * OUT_CH + lane * 4);
        x0 = (x0 > 0.f) ? x0 : 0.2f * x0;  float e0 = __expf(x0);
        x1 = (x1 > 0.f) ? x1 : 0.2f * x1;  float e1 = __expf(x1);
        x2 = (x2 > 0.f) ? x2 : 0.2f * x2;  float e2 = __expf(x2);
        x3 = (x3 > 0.f) ? x3 : 0.2f * x3;  float e3 = __expf(x3);
        den += (e0 + e1) + (e2 + e3);
        a0 = fmaf(e0, h0.x, a0); a1 = fmaf(e0, h0.y, a1);
        a2 = fmaf(e0, h0.z, a2); a3 = fmaf(e0, h0.w, a3);
        a0 = fmaf(e1, h1.x, a0); a1 = fmaf(e1, h1.y, a1);
        a2 = fmaf(e1, h1.z, a2); a3 = fmaf(e1, h1.w, a3);
        a0 = fmaf(e2, h2.x, a0); a1 = fmaf(e2, h2.y, a1);
        a2 = fmaf(e2, h2.z, a2); a3 = fmaf(e2, h2.w, a3);
        a0 = fmaf(e3, h3.x, a0); a1 = fmaf(e3, h3.y, a1);
        a2 = fmaf(e3, h3.z, a2); a3 = fmaf(e3, h3.w, a3);
    }
    for (; j < j1; j++) {
        int s = g_csrc[j];
        float x = g_s2[s] + dv;
        x = (x > 0.f) ? x : 0.2f * x;
        float ea = __expf(x);
        den += ea;
        float4 hv = *(const float4*)(g_h2 + (size_t)s * OUT_CH + lane * 4);
        a0 = fmaf(ea, hv.x, a0);
        a1 = fmaf(ea, hv.y, a1);
        a2 = fmaf(ea, hv.z, a2);
        a3 = fmaf(ea, hv.w, a3);
    }
    float inv = 1.f / den;
    int c = lane * 4;
    float v0 = a0 * inv + bias[c + 0];
    float v1 = a1 * inv + bias[c + 1];
    float v2 = a2 * inv + bias[c + 2];
    float v3 = a3 * inv + bias[c + 3];
    v0 = (v0 > 0.f) ? v0 : expm1f(v0);
    v1 = (v1 > 0.f) ? v1 : expm1f(v1);
    v2 = (v2 > 0.f) ? v2 : expm1f(v2);
    v3 = (v3 > 0.f) ? v3 : expm1f(v3);
    *(float4*)(out + (size_t)gw * OUT_CH + c) = make_float4(v0, v1, v2, v3);
}

// ------------------ launch ---------------------------------------------------
extern "C" void kernel_launch(void* const* d_in, const int* in_sizes, int n_in,
                              void* d_out, int out_size)
{
    const float* x   = (const float*)d_in[0];
    const int*   ei  = (const int*)  d_in[1];
    const float* W1  = (const float*)d_in[2];
    const float* as1 = (const float*)d_in[3];
    const float* ad1 = (const float*)d_in[4];
    const float* b1  = (const float*)d_in[5];
    const float* W2  = (const float*)d_in[6];
    const float* as2 = (const float*)d_in[7];
    const float* ad2 = (const float*)d_in[8];
    const float* b2  = (const float*)d_in[9];
    float* out = (float*)d_out;

    int n = in_sizes[0] / IN_CH;
    int e = in_sizes[1] / 2;
    const int* src = ei;
    const int* dst = ei + e;

    void *p_h1, *p_h1b, *p_h2, *p_s1, *p_d1, *p;
    cudaGetSymbolAddress(&p_h1,  g_h1);
    cudaGetSymbolAddress(&p_h1b, g_h1b);
    cudaGetSymbolAddress(&p_h2,  g_h2);
    cudaGetSymbolAddress(&p_s1,  g_s1);
    cudaGetSymbolAddress(&p_d1,  g_d1);

    cudaFuncSetAttribute(gemm_tf32,
                         cudaFuncAttributeMaxDynamicSharedMemorySize, GEMM_SMEM);

    // ---- CSR build (shared by both layers) ----
    cudaGetSymbolAddress(&p, g_deg);
    cudaMemsetAsync(p, 0, (size_t)n * 4);
    count_kernel<<<(e + n + 255) / 256, 256>>>(dst, e, n);
    int nb = (n + 4095) / 4096;
    scan1_kernel<<<nb, 1024>>>(n);
    scan2_kernel<<<1, 32>>>(nb, n);
    scan3_kernel<<<(n + 255) / 256, 256>>>(n);
    scatter_kernel<<<(e + n + 255) / 256, 256>>>(src, dst, e, n);

    // ---- layer 1 (GEMM with fused attention dots) ----
    {
        dim3 grid((n + GBM - 1) / GBM, H1DIM / GBN);
        gemm_tf32<<<grid, 256, GEMM_SMEM>>>(x, W1, (float*)p_h1, n, H1DIM, IN_CH,
                                            as1, ad1, (float*)p_s1, (float*)p_d1, 1);
    }
    gather1_kernel<<<(n * 32 + 255) / 256, 256>>>(b1, n);

    // ---- layer 2 ----
    {
        dim3 grid((n + GBM - 1) / GBM, OUT_CH / GBN);
        gemm_tf32<<<grid, 256, GEMM_SMEM>>>((const float*)p_h1b, W2, (float*)p_h2,
                                            n, OUT_CH, H1DIM,
                                            as2, ad2, nullptr, nullptr, 0);
    }
    sd2_kernel<<<(n * 32 + 255) / 256, 256>>>(as2, ad2, n);
    gather2_kernel<<<(n * 32 + 255) / 256, 256>>>(b2, out, n);
}